// round 1
// baseline (speedup 1.0000x reference)
#include <cuda_runtime.h>
#include <math.h>

// Problem constants (fixed shapes for this problem instance)
#define NN   50000
#define EE   400000
#define MEMF 64
#define EFD  32
#define TFD  32
#define HD   128     // H*D
#define HIDD 512
#define QIN  96      // MEM + TF
#define KIN  128     // MEM + EF + TF

// ---------------- device scratch (static; no runtime allocation) ----------------
__device__ float g_Q[NN * HD];        // per-node query projection   (25.6 MB)
__device__ float g_K[NN * HD];        // per-node key (mem part)     (25.6 MB)
__device__ float g_agg[NN * HD];      // normalized aggregation      (25.6 MB)
__device__ float g_WqT[64 * 128];     // Wq mem-part transposed [i][j]
__device__ float g_WkT[128 * 128];    // Wk transposed [i][j]  (rows 0-63 mem, 64-95 ef, 96-127 time)
__device__ float g_W1T[192 * 512];    // W1 transposed [k][j]
__device__ float g_qc[128];           // qconst[j] = sum_t Wq[j,64+t]*cos(tb[t])
__device__ int   g_cnt[NN];
__device__ int   g_off[NN];
__device__ int   g_cur[NN];
__device__ int   g_eidx[EE];

// ---------------- tiny setup kernels ----------------
__global__ void k_zero() {
    int i = blockIdx.x * blockDim.x + threadIdx.x;
    if (i < NN) g_cnt[i] = 0;
}

__global__ void k_trans(const float* __restrict__ Wq, const float* __restrict__ Wk,
                        const float* __restrict__ W1) {
    int i = blockIdx.x * blockDim.x + threadIdx.x;
    if (i < 192 * 512) {
        int k = i / 512, j = i % 512;
        g_W1T[i] = W1[j * 192 + k];
    }
    int i2 = i - 192 * 512;
    if (i2 >= 0 && i2 < 128 * 128) {
        int r = i2 / 128, j = i2 % 128;
        g_WkT[i2] = Wk[j * 128 + r];
    }
    int i3 = i2 - 128 * 128;
    if (i3 >= 0 && i3 < 64 * 128) {
        int r = i3 / 128, j = i3 % 128;
        g_WqT[i3] = Wq[j * QIN + r];
    }
}

__global__ void k_qconst(const float* __restrict__ Wq, const float* __restrict__ time_b) {
    int j = threadIdx.x;  // 128 threads
    float s = 0.f;
    for (int t = 0; t < TFD; t++) s += Wq[j * QIN + MEMF + t] * cosf(time_b[t]);
    g_qc[j] = s;
}

__global__ void k_count(const int* __restrict__ dst) {
    int e = blockIdx.x * blockDim.x + threadIdx.x;
    if (e < EE) atomicAdd(&g_cnt[dst[e]], 1);
}

__global__ void k_scan() {  // single block, 1024 threads
    __shared__ int ss[1024];
    int t = threadIdx.x;
    const int CH = (NN + 1023) / 1024;  // 49
    int b = t * CH;
    int s = 0;
    for (int i = 0; i < CH; i++) {
        int idx = b + i;
        if (idx < NN) s += g_cnt[idx];
    }
    ss[t] = s;
    __syncthreads();
    for (int o = 1; o < 1024; o <<= 1) {
        int v = (t >= o) ? ss[t - o] : 0;
        __syncthreads();
        ss[t] += v;
        __syncthreads();
    }
    int pre = t ? ss[t - 1] : 0;
    for (int i = 0; i < CH; i++) {
        int idx = b + i;
        if (idx < NN) {
            int c = g_cnt[idx];
            g_off[idx] = pre;
            g_cur[idx] = pre;
            pre += c;
        }
    }
}

__global__ void k_scatter(const int* __restrict__ dst) {
    int e = blockIdx.x * blockDim.x + threadIdx.x;
    if (e < EE) {
        int p = atomicAdd(&g_cur[dst[e]], 1);
        g_eidx[p] = e;
    }
}

// ---------------- node precompute: Qnode, Knode ----------------
__global__ __launch_bounds__(256) void k_node(const float* __restrict__ memory) {
    __shared__ float sWq[64 * 128];
    int tid = threadIdx.x;
    for (int i = tid; i < 64 * 128; i += 256) sWq[i] = g_WqT[i];
    __syncthreads();
    int l = tid & 31, w = tid >> 5;
    int warp = blockIdx.x * 8 + w;
    int stride = gridDim.x * 8;
    const unsigned FULL = 0xffffffffu;
    for (int node = warp; node < NN; node += stride) {
        float2 m2 = *(const float2*)(memory + node * MEMF + 2 * l);
        float4 aQ = *(const float4*)(g_qc + 4 * l);
        float4 aK = make_float4(0.f, 0.f, 0.f, 0.f);
#pragma unroll 8
        for (int i = 0; i < 32; i++) {
            float va = __shfl_sync(FULL, m2.x, i);
            float vb = __shfl_sync(FULL, m2.y, i);
            float4 qa = *(const float4*)(sWq + (2 * i) * 128 + 4 * l);
            float4 qb = *(const float4*)(sWq + (2 * i + 1) * 128 + 4 * l);
            float4 ka = *(const float4*)(g_WkT + (2 * i) * 128 + 4 * l);
            float4 kb = *(const float4*)(g_WkT + (2 * i + 1) * 128 + 4 * l);
            aQ.x = fmaf(va, qa.x, fmaf(vb, qb.x, aQ.x));
            aQ.y = fmaf(va, qa.y, fmaf(vb, qb.y, aQ.y));
            aQ.z = fmaf(va, qa.z, fmaf(vb, qb.z, aQ.z));
            aQ.w = fmaf(va, qa.w, fmaf(vb, qb.w, aQ.w));
            aK.x = fmaf(va, ka.x, fmaf(vb, kb.x, aK.x));
            aK.y = fmaf(va, ka.y, fmaf(vb, kb.y, aK.y));
            aK.z = fmaf(va, ka.z, fmaf(vb, kb.z, aK.z));
            aK.w = fmaf(va, ka.w, fmaf(vb, kb.w, aK.w));
        }
        *(float4*)(g_Q + node * 128 + 4 * l) = aQ;
        *(float4*)(g_K + node * 128 + 4 * l) = aK;
    }
}

// ---------------- main edge pass: warp per dst, no float atomics ----------------
__global__ __launch_bounds__(256) void k_edge(const int* __restrict__ src,
                                              const float* __restrict__ ts,
                                              const float* __restrict__ efeats,
                                              const float* __restrict__ ets,
                                              const float* __restrict__ time_w,
                                              const float* __restrict__ time_b) {
    __shared__ float sWef[32 * 128];
    __shared__ float sWt[32 * 128];
    int tid = threadIdx.x;
    for (int i = tid; i < 32 * 128; i += 256) {
        sWef[i] = g_WkT[64 * 128 + i];
        sWt[i]  = g_WkT[96 * 128 + i];
    }
    __syncthreads();
    int l = tid & 31, w = tid >> 5;
    float tw = __ldg(&time_w[l]);
    float tb = __ldg(&time_b[l]);
    int warp = blockIdx.x * 8 + w;
    int stride = gridDim.x * 8;
    const unsigned FULL = 0xffffffffu;

    for (int node = warp; node < NN; node += stride) {
        int base = g_off[node];
        int deg = g_cnt[node];
        float4 q = *(const float4*)(g_Q + node * 128 + 4 * l);
        float4 acc = make_float4(0.f, 0.f, 0.f, 0.f);
        float den = 0.f;

        for (int t0 = 0; t0 < deg; t0 += 4) {
            float4 kh[4];
            float efv[4], ctv[4];
            bool valid[4];
#pragma unroll
            for (int s = 0; s < 4; s++) {
                bool v = (t0 + s) < deg;
                int e = g_eidx[base + (v ? (t0 + s) : 0)];
                int sn = __ldg(&src[e]);
                float td = __ldg(&ets[e]) - __ldg(&ts[sn]);
                efv[s] = __ldg(&efeats[e * EFD + l]);
                ctv[s] = cosf(td * tw + tb);
                kh[s] = *(const float4*)(g_K + sn * 128 + 4 * l);
                valid[s] = v;
            }
#pragma unroll 8
            for (int i = 0; i < 32; i++) {
                float4 wef = *(const float4*)(sWef + i * 128 + 4 * l);
                float4 wt  = *(const float4*)(sWt + i * 128 + 4 * l);
#pragma unroll
                for (int s = 0; s < 4; s++) {
                    float vef = __shfl_sync(FULL, efv[s], i);
                    float vct = __shfl_sync(FULL, ctv[s], i);
                    kh[s].x = fmaf(vef, wef.x, fmaf(vct, wt.x, kh[s].x));
                    kh[s].y = fmaf(vef, wef.y, fmaf(vct, wt.y, kh[s].y));
                    kh[s].z = fmaf(vef, wef.z, fmaf(vct, wt.z, kh[s].z));
                    kh[s].w = fmaf(vef, wef.w, fmaf(vct, wt.w, kh[s].w));
                }
            }
#pragma unroll
            for (int s = 0; s < 4; s++) {
                float p = q.x * kh[s].x + q.y * kh[s].y + q.z * kh[s].z + q.w * kh[s].w;
                // reduce over the 4 lanes of this head group (lanes 4h..4h+3)
                p += __shfl_xor_sync(FULL, p, 1);
                p += __shfl_xor_sync(FULL, p, 2);
                float eh = valid[s] ? expf(p) : 0.f;
                acc.x = fmaf(eh, kh[s].x, acc.x);
                acc.y = fmaf(eh, kh[s].y, acc.y);
                acc.z = fmaf(eh, kh[s].z, acc.z);
                acc.w = fmaf(eh, kh[s].w, acc.w);
                den += eh;
            }
        }
        float inv = 1.f / (den * 4.0f);  // includes /sqrt(D), D=16
        acc.x *= inv; acc.y *= inv; acc.z *= inv; acc.w *= inv;
        *(float4*)(g_agg + node * 128 + 4 * l) = acc;
    }
}

// ---------------- merge MLP: 32 nodes per block, fused relu + second GEMM ----------------
__global__ __launch_bounds__(512) void k_merge(const float* __restrict__ memory,
                                               const float* __restrict__ b1,
                                               const float* __restrict__ W2,
                                               const float* __restrict__ b2,
                                               float* __restrict__ out) {
    __shared__ float sX[192 * 36];   // X^T tile: [k][node], padded to 36
    __shared__ float sU[4224];       // union: W1 chunk [8][512] | hid chunk [32][132]
    int tid = threadIdx.x;
    int n0 = blockIdx.x * 32;

    // stage X = [agg | memory] transposed (k-major)
    for (int idx = tid; idx < 32 * 192; idx += 512) {
        int n = idx / 192, k = idx % 192;
        int node = n0 + n;
        float v = 0.f;
        if (node < NN) v = (k < 128) ? g_agg[node * 128 + k] : memory[node * MEMF + (k - 128)];
        sX[k * 36 + n] = v;
    }

    int cg = tid & 127, ng = tid >> 7;   // col group (4 cols), node group (8 nodes)
    int j0 = cg * 4, m0 = ng * 8;
    float acc[8][4];
#pragma unroll
    for (int mi = 0; mi < 8; mi++)
#pragma unroll
        for (int ci = 0; ci < 4; ci++) acc[mi][ci] = 0.f;

    const int KC = 8;
    for (int c = 0; c < 192 / KC; c++) {
        __syncthreads();
        for (int idx = tid; idx < KC * 512; idx += 512) {
            int kk = idx >> 9, j = idx & 511;
            sU[kk * 512 + j] = g_W1T[(c * KC + kk) * 512 + j];
        }
        __syncthreads();
#pragma unroll
        for (int kk = 0; kk < KC; kk++) {
            int k = c * KC + kk;
            float4 wv = *(const float4*)(sU + kk * 512 + j0);
            float4 xa = *(const float4*)(sX + k * 36 + m0);
            float4 xb = *(const float4*)(sX + k * 36 + m0 + 4);
            float xm[8] = {xa.x, xa.y, xa.z, xa.w, xb.x, xb.y, xb.z, xb.w};
#pragma unroll
            for (int mi = 0; mi < 8; mi++) {
                acc[mi][0] = fmaf(xm[mi], wv.x, acc[mi][0]);
                acc[mi][1] = fmaf(xm[mi], wv.y, acc[mi][1]);
                acc[mi][2] = fmaf(xm[mi], wv.z, acc[mi][2]);
                acc[mi][3] = fmaf(xm[mi], wv.w, acc[mi][3]);
            }
        }
    }

    // bias + relu (hid stays in registers)
    float4 bb = *(const float4*)(b1 + j0);
    float bm[4] = {bb.x, bb.y, bb.z, bb.w};
#pragma unroll
    for (int mi = 0; mi < 8; mi++)
#pragma unroll
        for (int ci = 0; ci < 4; ci++) {
            float h = acc[mi][ci] + bm[ci];
            acc[mi][ci] = h > 0.f ? h : 0.f;
        }

    // second GEMM: out[m][o] = sum_j hid[m][j] * W2[o][j], chunked over j
    int mo_m = tid >> 4, mo_o = tid & 15;
    float* sHc = sU;          // [32][132]
    float* sW2c = sX;         // [16][132] (sX region is free now)
    float oacc = 0.f;
    for (int c = 0; c < 4; c++) {
        __syncthreads();
        if ((cg >> 5) == c) {
            int jj = (cg & 31) * 4;
#pragma unroll
            for (int mi = 0; mi < 8; mi++) {
                *(float4*)(sHc + (m0 + mi) * 132 + jj) =
                    make_float4(acc[mi][0], acc[mi][1], acc[mi][2], acc[mi][3]);
            }
        }
        for (int idx = tid; idx < 16 * 128; idx += 512) {
            int o = idx >> 7, jj = idx & 127;
            sW2c[o * 132 + jj] = W2[o * 512 + c * 128 + jj];
        }
        __syncthreads();
#pragma unroll 8
        for (int j4 = 0; j4 < 32; j4++) {
            float4 h4 = *(const float4*)(sHc + mo_m * 132 + j4 * 4);
            float4 w4 = *(const float4*)(sW2c + mo_o * 132 + j4 * 4);
            oacc += h4.x * w4.x + h4.y * w4.y + h4.z * w4.z + h4.w * w4.w;
        }
    }
    int node = n0 + mo_m;
    if (node < NN) out[node * 16 + mo_o] = oacc + __ldg(&b2[mo_o]);
}

// ---------------- launch ----------------
extern "C" void kernel_launch(void* const* d_in, const int* in_sizes, int n_in,
                              void* d_out, int out_size) {
    const int*   src    = (const int*)d_in[0];
    const int*   dst    = (const int*)d_in[1];
    const float* memory = (const float*)d_in[2];
    const float* ts     = (const float*)d_in[3];
    const float* efeats = (const float*)d_in[4];
    const float* ets    = (const float*)d_in[5];
    const float* Wq     = (const float*)d_in[6];
    const float* Wk     = (const float*)d_in[7];
    const float* W1     = (const float*)d_in[8];
    const float* b1     = (const float*)d_in[9];
    const float* W2     = (const float*)d_in[10];
    const float* b2     = (const float*)d_in[11];
    const float* time_w = (const float*)d_in[12];
    const float* time_b = (const float*)d_in[13];
    float* out = (float*)d_out;

    k_zero<<<(NN + 255) / 256, 256>>>();
    k_trans<<<480, 256>>>(Wq, Wk, W1);
    k_qconst<<<1, 128>>>(Wq, time_b);
    k_count<<<(EE + 255) / 256, 256>>>(dst);
    k_scan<<<1, 1024>>>();
    k_scatter<<<(EE + 255) / 256, 256>>>(dst);
    k_node<<<592, 256>>>(memory);
    k_edge<<<592, 256>>>(src, ts, efeats, ets, time_w, time_b);
    k_merge<<<(NN + 31) / 32, 512>>>(memory, b1, W2, b2, out);
}